// round 2
// baseline (speedup 1.0000x reference)
#include <cuda_runtime.h>
#include <math.h>

#define BB 16
#define HH 512
#define WW 512

// Scratch (no cudaMalloc allowed): d1 = per-column squared vertical distance
__device__ float g_d1[BB * HH * WW];          // 16.8 MB
__device__ float g_partial[BB * HH];           // per-row-block partial sums

// ---------------------------------------------------------------------------
// Kernel 1: column pass.
// d1[b,i,j] = min( (i - f)^2, (bk - i)^2 )
//   f  = nearest fg row at-or-above (init -BIG = -2048, BIG = 2*(H+W))
//   bk = nearest fg row at-or-below (init BIG + H = 2560)
// Exactly replicates the reference's cummax/cummin construction (incl. the
// sentinel behavior for columns with no foreground).
// Grid: (WW/64, BB); block: 64 threads, one thread per column.
// ---------------------------------------------------------------------------
__global__ void col_pass(const int* __restrict__ gt) {
    int b = blockIdx.y;
    int j = blockIdx.x * 64 + threadIdx.x;
    const int* g = gt + (size_t)b * HH * WW;
    float* d1 = g_d1 + (size_t)b * HH * WW;

    float f = -2048.0f;  // -BIG
    #pragma unroll 4
    for (int i = 0; i < HH; ++i) {
        if (g[i * WW + j] != 0) f = (float)i;
        float df = (float)i - f;
        d1[i * WW + j] = df * df;
    }
    float bk = 2560.0f;  // BIG + H
    #pragma unroll 4
    for (int i = HH - 1; i >= 0; --i) {
        if (g[i * WW + j] != 0) bk = (float)i;
        float db = bk - (float)i;
        float v = db * db;
        float cur = d1[i * WW + j];
        d1[i * WW + j] = fminf(cur, v);
    }
}

// ---------------------------------------------------------------------------
// Kernel 2: exact 1D min-plus along rows with expanding-radius early exit,
// then val = sqrt(d2) * probs[b,0,i,j], block-reduced to g_partial[row].
// Exactness: best(r) = min over |j'-j| <= r of d1[j'] + (j'-j)^2. Any j' at
// distance >= r contributes >= r^2, so once r^2 >= best no improvement is
// possible (d1 >= 0). Worst case degrades to a full scan — still exact.
// Grid: BB*HH blocks; block: 512 threads (one per output column).
// ---------------------------------------------------------------------------
__global__ void row_pass(const float* __restrict__ probs) {
    __shared__ float s[WW];
    __shared__ float wsum[16];

    int row = blockIdx.x;            // b*HH + i
    int b = row >> 9;                // /512
    int i = row & (HH - 1);
    int j = threadIdx.x;

    const float* d1row = g_d1 + (size_t)row * WW;
    s[j] = d1row[j];
    __syncthreads();

    float best = s[j];
    for (int r = 1; r < WW; ++r) {
        float rr = (float)(r * r);
        if (rr >= best) break;
        int jl = j - r;
        int jr = j + r;
        if (jl >= 0) best = fminf(best, s[jl] + rr);
        if (jr < WW) best = fminf(best, s[jr] + rr);
    }

    // probs layout [B, 2, H, W], channel 0
    float p = probs[(((size_t)b * 2) * HH + i) * WW + j];
    float val = sqrtf(best) * p;

    // block tree reduction (deterministic)
    #pragma unroll
    for (int off = 16; off > 0; off >>= 1)
        val += __shfl_down_sync(0xffffffffu, val, off);
    if ((j & 31) == 0) wsum[j >> 5] = val;
    __syncthreads();
    if (j < 16) {
        float v = wsum[j];
        #pragma unroll
        for (int off = 8; off > 0; off >>= 1)
            v += __shfl_down_sync(0x0000ffffu, v, off);
        if (j == 0) g_partial[row] = v;
    }
}

// ---------------------------------------------------------------------------
// Kernel 3: final reduction of BB*HH = 8192 partials -> mean.
// ---------------------------------------------------------------------------
__global__ void final_reduce(float* __restrict__ out) {
    __shared__ float wsum[32];
    int t = threadIdx.x;  // 1024 threads
    float v = 0.0f;
    #pragma unroll
    for (int k = t; k < BB * HH; k += 1024) v += g_partial[k];
    #pragma unroll
    for (int off = 16; off > 0; off >>= 1)
        v += __shfl_down_sync(0xffffffffu, v, off);
    if ((t & 31) == 0) wsum[t >> 5] = v;
    __syncthreads();
    if (t < 32) {
        float w = wsum[t];
        #pragma unroll
        for (int off = 16; off > 0; off >>= 1)
            w += __shfl_down_sync(0xffffffffu, w, off);
        if (t == 0) out[0] = w * (1.0f / (float)(BB * HH * WW));
    }
}

extern "C" void kernel_launch(void* const* d_in, const int* in_sizes, int n_in,
                              void* d_out, int out_size) {
    const float* probs = (const float*)d_in[0];
    const int*   gt    = (const int*)d_in[1];
    float* out = (float*)d_out;

    dim3 g1(WW / 64, BB);
    col_pass<<<g1, 64>>>(gt);
    row_pass<<<BB * HH, WW>>>(probs);
    final_reduce<<<1, 1024>>>(out);
}

// round 8
// speedup vs baseline: 2.5666x; 2.5666x over previous
#include <cuda_runtime.h>
#include <math.h>

#define BB 16
#define HH 512
#define WW 512
#define WORDS_PER_ROW 16   // 512 / 32

// Scratch (no cudaMalloc allowed)
__device__ unsigned g_bits[BB * HH * WORDS_PER_ROW];  // 512 KB bitmask of gt!=0
__device__ float g_partial[BB * 16 * 16];             // per-tile partials (4096)

// ---------------------------------------------------------------------------
// Kernel 1: pack gt (int32) into a bitmask, 1 bit per pixel.
// Each thread reads 4 ints (int4); each warp emits 4 consecutive 32-bit words
// via 4 ballots. Coalesced 16B loads, 1/4 the instruction count of scalar.
// ---------------------------------------------------------------------------
__global__ void pack_bits(const int4* __restrict__ gt4) {
    int t = blockIdx.x * blockDim.x + threadIdx.x;   // one thread per 4 pixels
    int4 v = gt4[t];
    unsigned b0 = __ballot_sync(0xffffffffu, v.x != 0);
    unsigned b1 = __ballot_sync(0xffffffffu, v.y != 0);
    unsigned b2 = __ballot_sync(0xffffffffu, v.z != 0);
    unsigned b3 = __ballot_sync(0xffffffffu, v.w != 0);
    if ((threadIdx.x & 31) == 0) {
        // lanes 0..31 of this warp cover pixels [base, base+128); interleaved:
        // pixel index = base + lane*4 + c  -> bit (lane) of word (base/32 + c)... no:
        // pixel p = t*4 + c with t = warpbase + lane, so for component c the 32
        // ballot bits are pixels {warpbase*4 + lane*4 + c}. That is NOT a
        // contiguous 32-pixel word. Handle below with a transpose-free scheme.
        // (dummy write avoided; real packing done in pack_bits_fix)
        (void)b0; (void)b1; (void)b2; (void)b3;
    }
    // NOTE: interleaving makes ballots non-contiguous; instead each thread
    // packs its own 4 bits and a warp-level OR-reduce assembles words.
    unsigned nib = (v.x != 0 ? 1u : 0u) | (v.y != 0 ? 2u : 0u)
                 | (v.z != 0 ? 4u : 0u) | (v.w != 0 ? 8u : 0u);
    // word index = t / 8 (8 threads' nibbles per 32-bit word)
    unsigned grp = (threadIdx.x >> 3) & 3;           // position within... see below
    // Assemble: threads 8k..8k+7 form one word; use shfl to gather.
    unsigned word = nib << ((threadIdx.x & 7) * 4);
    #pragma unroll
    for (int off = 1; off < 8; off <<= 1)
        word |= __shfl_xor_sync(0xffffffffu, word, off);
    if ((threadIdx.x & 7) == 0) g_bits[t >> 3] = word;
    (void)grp;
}

// ---------------------------------------------------------------------------
// Exact global fallback: scan full-image bitmask with distance pruning.
// Only reachable when no foreground within Chebyshev radius 16 of the pixel
// (probability ~2^-1089 for Bernoulli(1/2) input) — correctness insurance.
// ---------------------------------------------------------------------------
__device__ __noinline__ float global_fallback(int b, int gi, int gj, float best) {
    const unsigned* base = g_bits + ((size_t)b * HH * WORDS_PER_ROW);
    for (int dd = 0; dd < HH; ++dd) {
        float dd2 = (float)(dd * dd);
        if (dd2 >= best) break;
        for (int sgn = 0; sgn < 2; ++sgn) {
            if (sgn && dd == 0) continue;
            int r = sgn ? gi + dd : gi - dd;
            if (r < 0 || r >= HH) continue;
            const unsigned* row = base + r * WORDS_PER_ROW;
            for (int w = 0; w < WORDS_PER_ROW; ++w) {
                unsigned word = row[w];
                while (word) {
                    int bit = __ffs(word) - 1;
                    word &= word - 1;
                    float dj = (float)((w << 5) + bit - gj);
                    best = fminf(best, dd2 + dj * dj);
                }
            }
        }
    }
    return best;
}

// ---------------------------------------------------------------------------
// Kernel 2: fused exact EDT (expanding Chebyshev rings on a 64x64 bit window)
// + sqrt + probs multiply + block reduction.
// Grid: (W/32, H/32, B); block 256 threads; thread handles 4 pixels.
// Window = tile + 16-px halo. Exactness: any fg outside the window has
// Chebyshev distance >= 17 => squared Euclid >= 289; if in-window best <= 289
// it is globally optimal, else fall back to the (exact) global scan.
// ---------------------------------------------------------------------------
__global__ void fused_edt(const float* __restrict__ probs) {
    __shared__ unsigned long long s[64];
    __shared__ float wsum[8];

    int b   = blockIdx.z;
    int ti0 = blockIdx.y * 32;
    int tj0 = blockIdx.x * 32;
    int tid = threadIdx.x;

    // Load 64-row x 64-bit window; rows/cols outside the image are 0 (no fg).
    // Bit l of s[row] = global column (tj0 - 16 + l).
    if (tid < 64) {
        int gi = ti0 - 16 + tid;
        unsigned long long v = 0ull;
        if (gi >= 0 && gi < HH) {
            const unsigned* bp = g_bits + ((size_t)(b * HH + gi)) * WORDS_PER_ROW;
            int w0 = tj0 >> 5;
            unsigned m1 = (w0 > 0)                 ? bp[w0 - 1] : 0u;
            unsigned c0 = bp[w0];
            unsigned p1 = (w0 < WORDS_PER_ROW - 1) ? bp[w0 + 1] : 0u;
            v = ((unsigned long long)m1 >> 16)
              | ((unsigned long long)c0 << 16)
              | ((unsigned long long)p1 << 48);
        }
        s[tid] = v;
    }
    __syncthreads();

    int tj   = tid & 31;
    int trow = tid >> 5;
    float acc = 0.0f;

    #pragma unroll 1
    for (int k = 0; k < 4; ++k) {
        int ti = trow * 4 + k;
        int li = 16 + ti;       // local row in window
        int lj = 16 + tj;       // local col in window, in [16, 47]
        int gi = ti0 + ti;
        int gj = tj0 + tj;

        float best;
        if ((s[li] >> lj) & 1ull) {
            best = 0.0f;
        } else {
            best = 1e30f;
            #pragma unroll 1
            for (int r = 1; r <= 16; ++r) {
                float rr = (float)(r * r);
                if (rr >= best) break;
                // top + bottom rows of the ring (|di| = r, dj in [-r, r]):
                // min |dj| among set bits of the OR of the two rows.
                int sh = lj - r;                       // >= 0
                unsigned long long m = (s[li - r] | s[li + r]) >> sh;
                m &= (1ull << (2 * r + 1)) - 1ull;     // width <= 33 bits
                if (m) {
                    unsigned long long right = m >> r;                        // dj >= 0
                    unsigned long long left  = m & ((1ull << (r + 1)) - 1ull); // dj <= 0
                    int dj = 64;
                    if (right) dj = __ffsll((long long)right) - 1;
                    if (left) {
                        int p = 63 - __clzll((long long)left);
                        int dl = r - p;
                        dj = dj < dl ? dj : dl;
                    }
                    best = fminf(best, rr + (float)(dj * dj));
                }
                // side columns (dj = +-r, |di| < r); di ascending => first hit min.
                if (rr < best) {
                    int shl = lj - r, shr = lj + r;    // shr <= 63
                    for (int di = 0; di < r; ++di) {
                        unsigned long long ra = s[li - di] | s[li + di];
                        if (((ra >> shl) | (ra >> shr)) & 1ull) {
                            best = fminf(best, rr + (float)(di * di));
                            break;
                        }
                    }
                }
            }
            if (best > 289.0f)
                best = global_fallback(b, gi, gj, best);
        }

        // probs layout [B, 2, H, W], channel 0
        float p = probs[(((size_t)b * 2) * HH + gi) * WW + gj];
        acc += sqrtf(best) * p;
    }

    // deterministic block reduction (8 warps)
    #pragma unroll
    for (int off = 16; off > 0; off >>= 1)
        acc += __shfl_down_sync(0xffffffffu, acc, off);
    if ((tid & 31) == 0) wsum[tid >> 5] = acc;
    __syncthreads();
    if (tid < 8) {
        float v = wsum[tid];
        #pragma unroll
        for (int off = 4; off > 0; off >>= 1)
            v += __shfl_down_sync(0x000000ffu, v, off);
        if (tid == 0)
            g_partial[(blockIdx.z * 16 + blockIdx.y) * 16 + blockIdx.x] = v;
    }
}

// ---------------------------------------------------------------------------
// Kernel 3: final reduction of 4096 partials -> mean.
// ---------------------------------------------------------------------------
__global__ void final_reduce(float* __restrict__ out) {
    __shared__ float wsum[8];
    int t = threadIdx.x;  // 256 threads
    float v = 0.0f;
    #pragma unroll
    for (int k = t; k < BB * 16 * 16; k += 256) v += g_partial[k];
    #pragma unroll
    for (int off = 16; off > 0; off >>= 1)
        v += __shfl_down_sync(0xffffffffu, v, off);
    if ((t & 31) == 0) wsum[t >> 5] = v;
    __syncthreads();
    if (t < 8) {
        float w = wsum[t];
        #pragma unroll
        for (int off = 4; off > 0; off >>= 1)
            w += __shfl_down_sync(0x000000ffu, w, off);
        if (t == 0) out[0] = w * (1.0f / (float)((size_t)BB * HH * WW));
    }
}

extern "C" void kernel_launch(void* const* d_in, const int* in_sizes, int n_in,
                              void* d_out, int out_size) {
    const float* probs = (const float*)d_in[0];
    const int*   gt    = (const int*)d_in[1];
    float* out = (float*)d_out;

    // 4 pixels per thread: 4194304 / 4 / 256 = 4096 blocks
    pack_bits<<<(BB * HH * WW) / 4 / 256, 256>>>((const int4*)gt);
    dim3 grid(WW / 32, HH / 32, BB);
    fused_edt<<<grid, 256>>>(probs);
    final_reduce<<<1, 256>>>(out);
}

// round 9
// speedup vs baseline: 3.6671x; 1.4288x over previous
#include <cuda_runtime.h>
#include <math.h>

#define BB 16
#define HH 512
#define WW 512
#define WORDS_PER_ROW 16   // 512 / 32

// Scratch (no cudaMalloc allowed)
__device__ unsigned g_bits[BB * HH * WORDS_PER_ROW];  // 512 KB bitmask of gt!=0
__device__ float g_partial[BB * 16 * 16];             // per-tile partials (4096)

// ---------------------------------------------------------------------------
// Kernel 1: pack gt (int32) -> bitmask. One thread per output 32-bit word:
// 8 independent int4 loads (MLP=8), register assembly, single store.
// ---------------------------------------------------------------------------
__global__ void pack_bits(const int4* __restrict__ gt4) {
    int t = blockIdx.x * blockDim.x + threadIdx.x;   // one thread per 32 pixels
    const int4* p = gt4 + (size_t)t * 8;
    unsigned w = 0u;
    #pragma unroll
    for (int i = 0; i < 8; ++i) {
        int4 v = p[i];
        unsigned nib = (v.x != 0 ? 1u : 0u) | (v.y != 0 ? 2u : 0u)
                     | (v.z != 0 ? 4u : 0u) | (v.w != 0 ? 8u : 0u);
        w |= nib << (4 * i);
    }
    g_bits[t] = w;
}

// ---------------------------------------------------------------------------
// Exact global fallback: scan full-image bitmask with distance pruning.
// Reachable only when no fg within Chebyshev radius 16 — correctness insurance.
// ---------------------------------------------------------------------------
__device__ __noinline__ float global_fallback(int b, int gi, int gj, float best) {
    const unsigned* base = g_bits + ((size_t)b * HH * WORDS_PER_ROW);
    for (int dd = 0; dd < HH; ++dd) {
        float dd2 = (float)(dd * dd);
        if (dd2 >= best) break;
        for (int sgn = 0; sgn < 2; ++sgn) {
            if (sgn && dd == 0) continue;
            int r = sgn ? gi + dd : gi - dd;
            if (r < 0 || r >= HH) continue;
            const unsigned* row = base + r * WORDS_PER_ROW;
            for (int w = 0; w < WORDS_PER_ROW; ++w) {
                unsigned word = row[w];
                while (word) {
                    int bit = __ffs(word) - 1;
                    word &= word - 1;
                    float dj = (float)((w << 5) + bit - gj);
                    best = fminf(best, dd2 + dj * dj);
                }
            }
        }
    }
    return best;
}

// ---------------------------------------------------------------------------
// Cold path: exact expanding-Chebyshev-ring search starting at r=3 (5x5 was
// empty, so min d^2 >= 9). Same logic as the previously-passing kernel.
// ---------------------------------------------------------------------------
__device__ __noinline__ float ring_search(const unsigned long long* s,
                                          int li, int lj, int b, int gi, int gj) {
    float best = 1e30f;
    for (int r = 3; r <= 16; ++r) {
        float rr = (float)(r * r);
        if (rr >= best) break;
        int sh = lj - r;                       // >= 0 (lj >= 16)
        unsigned long long m = (s[li - r] | s[li + r]) >> sh;
        m &= (1ull << (2 * r + 1)) - 1ull;     // width <= 33 bits
        if (m) {
            unsigned long long right = m >> r;                         // dj >= 0
            unsigned long long left  = m & ((1ull << (r + 1)) - 1ull); // dj <= 0
            int dj = 64;
            if (right) dj = __ffsll((long long)right) - 1;
            if (left) {
                int pp = 63 - __clzll((long long)left);
                int dl = r - pp;
                dj = dj < dl ? dj : dl;
            }
            best = fminf(best, rr + (float)(dj * dj));
        }
        if (rr < best) {
            int shl = lj - r, shr = lj + r;    // shr <= 63
            for (int di = 0; di < r; ++di) {
                unsigned long long ra = s[li - di] | s[li + di];
                if (((ra >> shl) | (ra >> shr)) & 1ull) {
                    best = fminf(best, rr + (float)(di * di));
                    break;
                }
            }
        }
    }
    if (best > 289.0f)
        best = global_fallback(b, gi, gj, best);
    return best;
}

// ---------------------------------------------------------------------------
// Kernel 2: fused exact EDT + sqrt + probs multiply + block reduction.
// Hot path: branchless 5x5 neighborhood classifier over the bit window.
// Offsets with d^2 <= 8 all lie in the 5x5; bit i of a 5-bit field = column
// offset (i-2). Values ordered 0 < 1 < 2 < 4 < 5 < 8 give an exact priority
// select. If the whole 5x5 is empty (P = 2^-25 per pixel), fall into the
// exact ring search (r >= 3) and global fallback.
// Grid: (W/32, H/32, B); block 256; thread = 4 pixels in one column.
// ---------------------------------------------------------------------------
__global__ void fused_edt(const float* __restrict__ probs) {
    __shared__ unsigned long long s[64];
    __shared__ float wsum[8];

    int b   = blockIdx.z;
    int ti0 = blockIdx.y * 32;
    int tj0 = blockIdx.x * 32;
    int tid = threadIdx.x;

    // Load 64-row x 64-bit window; rows/cols outside the image are 0 (no fg).
    // Bit l of s[row] = global column (tj0 - 16 + l).
    if (tid < 64) {
        int gi = ti0 - 16 + tid;
        unsigned long long v = 0ull;
        if (gi >= 0 && gi < HH) {
            const unsigned* bp = g_bits + ((size_t)(b * HH + gi)) * WORDS_PER_ROW;
            int w0 = tj0 >> 5;
            unsigned m1 = (w0 > 0)                 ? bp[w0 - 1] : 0u;
            unsigned c0 = bp[w0];
            unsigned p1 = (w0 < WORDS_PER_ROW - 1) ? bp[w0 + 1] : 0u;
            v = ((unsigned long long)m1 >> 16)
              | ((unsigned long long)c0 << 16)
              | ((unsigned long long)p1 << 48);
        }
        s[tid] = v;
    }
    __syncthreads();

    int tj   = tid & 31;
    int trow = tid >> 5;
    int L    = 16 + trow * 4;          // local row of first pixel
    int lj   = 16 + tj;                // local col, in [16, 47]
    int sh   = lj - 2;                 // in [14, 45]

    // Shift the 8 needed rows once per thread (amortized over 4 pixels).
    unsigned x[8];
    #pragma unroll
    for (int m = 0; m < 8; ++m)
        x[m] = (unsigned)(s[L - 2 + m] >> sh) & 31u;

    float acc = 0.0f;

    #pragma unroll
    for (int k = 0; k < 4; ++k) {
        // bit i of these 5-bit fields = column offset (i-2)
        unsigned a5 = x[k + 2];                 // row offset 0
        unsigned c1 = x[k + 1] | x[k + 3];      // rows +-1
        unsigned c2 = x[k]     | x[k + 4];      // rows +-2

        unsigned h0 = a5 & 0x4u;                              // d^2 = 0
        unsigned h1 = (a5 & 0xAu)  | (c1 & 0x4u);             // d^2 = 1
        unsigned h2 = c1 & 0xAu;                              // d^2 = 2
        unsigned h4 = (a5 & 0x11u) | (c2 & 0x4u);             // d^2 = 4
        unsigned h5 = (c1 & 0x11u) | (c2 & 0xAu);             // d^2 = 5
        unsigned h8 = c2 & 0x11u;                             // d^2 = 8

        float dist;
        if (h0 | h1 | h2 | h4 | h5 | h8) {
            dist = h0 ? 0.0f
                 : h1 ? 1.0f
                 : h2 ? sqrtf(2.0f)
                 : h4 ? 2.0f
                 : h5 ? sqrtf(5.0f)
                 :      sqrtf(8.0f);
        } else {
            int li = L + k;
            int gi = ti0 + trow * 4 + k;
            int gj = tj0 + tj;
            dist = sqrtf(ring_search(s, li, lj, b, gi, gj));
        }

        // probs layout [B, 2, H, W], channel 0; lanes = consecutive columns.
        float p = probs[(((size_t)b * 2) * HH + (ti0 + trow * 4 + k)) * WW
                        + (tj0 + tj)];
        acc += dist * p;
    }

    // deterministic block reduction (8 warps)
    #pragma unroll
    for (int off = 16; off > 0; off >>= 1)
        acc += __shfl_down_sync(0xffffffffu, acc, off);
    if ((tid & 31) == 0) wsum[tid >> 5] = acc;
    __syncthreads();
    if (tid < 8) {
        float v = wsum[tid];
        #pragma unroll
        for (int off = 4; off > 0; off >>= 1)
            v += __shfl_down_sync(0x000000ffu, v, off);
        if (tid == 0)
            g_partial[(blockIdx.z * 16 + blockIdx.y) * 16 + blockIdx.x] = v;
    }
}

// ---------------------------------------------------------------------------
// Kernel 3: final reduction of 4096 partials -> mean.
// ---------------------------------------------------------------------------
__global__ void final_reduce(float* __restrict__ out) {
    __shared__ float wsum[8];
    int t = threadIdx.x;  // 256 threads
    float v = 0.0f;
    #pragma unroll
    for (int k = t; k < BB * 16 * 16; k += 256) v += g_partial[k];
    #pragma unroll
    for (int off = 16; off > 0; off >>= 1)
        v += __shfl_down_sync(0xffffffffu, v, off);
    if ((t & 31) == 0) wsum[t >> 5] = v;
    __syncthreads();
    if (t < 8) {
        float w = wsum[t];
        #pragma unroll
        for (int off = 4; off > 0; off >>= 1)
            w += __shfl_down_sync(0x000000ffu, w, off);
        if (t == 0) out[0] = w * (1.0f / (float)((size_t)BB * HH * WW));
    }
}

extern "C" void kernel_launch(void* const* d_in, const int* in_sizes, int n_in,
                              void* d_out, int out_size) {
    const float* probs = (const float*)d_in[0];
    const int*   gt    = (const int*)d_in[1];
    float* out = (float*)d_out;

    // one thread per 32 pixels: 4194304 / 32 / 256 = 512 blocks
    pack_bits<<<512, 256>>>((const int4*)gt);
    dim3 grid(WW / 32, HH / 32, BB);
    fused_edt<<<grid, 256>>>(probs);
    final_reduce<<<1, 256>>>(out);
}